// round 2
// baseline (speedup 1.0000x reference)
#include <cuda_runtime.h>

#define BATCH 8
#define SEQ   2048
#define EMB   1024
#define HS    64
#define MROWS (BATCH*SEQ)   // 16384

typedef unsigned long long u64;

// Scratch for Q/K/V projections (device globals: no allocation allowed)
__device__ float g_Q[(size_t)MROWS * HS];
__device__ float g_K[(size_t)MROWS * HS];
__device__ float g_V[(size_t)MROWS * HS];

// ---- packed f32x2 helpers (Blackwell FFMA2 path; ptxas never emits this from C++) ----
__device__ __forceinline__ u64 pack2(float x, float y) {
    u64 r; asm("mov.b64 %0, {%1, %2};" : "=l"(r) : "f"(x), "f"(y)); return r;
}
__device__ __forceinline__ void unpack2(u64 a, float& x, float& y) {
    asm("mov.b64 {%0, %1}, %2;" : "=f"(x), "=f"(y) : "l"(a));
}
__device__ __forceinline__ u64 fma2(u64 a, u64 b, u64 c) {
    u64 d; asm("fma.rn.f32x2 %0, %1, %2, %3;" : "=l"(d) : "l"(a), "l"(b), "l"(c)); return d;
}
__device__ __forceinline__ u64 mul2(u64 a, u64 b) {
    u64 d; asm("mul.rn.f32x2 %0, %1, %2;" : "=l"(d) : "l"(a), "l"(b)); return d;
}

// ============================================================================
// Projection GEMM: Y[M,64] = X[M,1024] @ W[1024,64]
// blockIdx.y: 0 -> Q (from index), 1 -> K (from memory), 2 -> V (from memory)
// Tile: 128 rows x 64 cols, BK=16. 256 threads, each computes 8 rows x 4 cols
// as 4 row-pair x 4 col f32x2 accumulators.
// ============================================================================
__global__ __launch_bounds__(256) void proj_kernel(
    const float* __restrict__ Xq, const float* __restrict__ Xkv,
    const float* __restrict__ Wq, const float* __restrict__ Wk,
    const float* __restrict__ Wv)
{
    __shared__ float As[16][132];  // [k][row], transposed so row pairs are contiguous
    __shared__ float Bs[16][64];   // [k][col]

    const int tid = threadIdx.x;
    const int which = blockIdx.y;
    const float* X = (which == 0) ? Xq : Xkv;
    const float* W = (which == 0) ? Wq : ((which == 1) ? Wk : Wv);
    float* Y = (which == 0) ? g_Q : ((which == 1) ? g_K : g_V);

    const int row0 = blockIdx.x * 128;
    const int ty = tid >> 4;     // 0..15 -> row group of 8
    const int tx = tid & 15;     // 0..15 -> col group of 4

    u64 acc[4][4];
    #pragma unroll
    for (int i = 0; i < 4; i++)
        #pragma unroll
        for (int j = 0; j < 4; j++) acc[i][j] = 0ull;

    for (int k0 = 0; k0 < EMB; k0 += 16) {
        // Load A tile (128x16) transposed into smem
        #pragma unroll
        for (int i = 0; i < 2; i++) {
            int f  = tid + i * 256;        // 0..511 float4s
            int r  = f >> 2;               // row 0..127
            int kq = (f & 3) << 2;         // k 0,4,8,12
            float4 v = *(const float4*)(X + (size_t)(row0 + r) * EMB + k0 + kq);
            As[kq + 0][r] = v.x; As[kq + 1][r] = v.y;
            As[kq + 2][r] = v.z; As[kq + 3][r] = v.w;
        }
        // Load W tile (16x64)
        {
            int kk = tid >> 4;
            int c  = (tid & 15) << 2;
            *(float4*)&Bs[kk][c] = *(const float4*)(W + (size_t)(k0 + kk) * HS + c);
        }
        __syncthreads();

        #pragma unroll
        for (int kk = 0; kk < 16; kk++) {
            u64 a[4];
            #pragma unroll
            for (int i = 0; i < 4; i++)
                a[i] = *(const u64*)&As[kk][ty * 8 + 2 * i];   // packed row pair
            float4 b = *(const float4*)&Bs[kk][tx * 4];
            u64 bs[4] = { pack2(b.x, b.x), pack2(b.y, b.y),
                          pack2(b.z, b.z), pack2(b.w, b.w) };
            #pragma unroll
            for (int i = 0; i < 4; i++)
                #pragma unroll
                for (int j = 0; j < 4; j++)
                    acc[i][j] = fma2(a[i], bs[j], acc[i][j]);
        }
        __syncthreads();
    }

    // Write back: rows row0 + ty*8 + 2i (+1), cols tx*4..tx*4+3
    #pragma unroll
    for (int i = 0; i < 4; i++) {
        float r0v[4], r1v[4];
        #pragma unroll
        for (int j = 0; j < 4; j++) unpack2(acc[i][j], r0v[j], r1v[j]);
        *(float4*)(Y + (size_t)(row0 + ty * 8 + 2 * i) * HS + tx * 4) =
            make_float4(r0v[0], r0v[1], r0v[2], r0v[3]);
        *(float4*)(Y + (size_t)(row0 + ty * 8 + 2 * i + 1) * HS + tx * 4) =
            make_float4(r1v[0], r1v[1], r1v[2], r1v[3]);
    }
}

// ============================================================================
// Flash attention (causal): per block one 64-row q-tile of one batch.
// Online softmax; K and V share one smem buffer (phase-separated).
// Thread (ty,tx): 4 q-rows (ty*4..+3) x 4 h-cols / 4 keys (tx*4..+3).
// ============================================================================
__global__ __launch_bounds__(256) void attn_kernel(float* __restrict__ out)
{
    __shared__ float Qs [64][64];  // [d][row]   (transposed)
    __shared__ float KVs[64][64];  // K phase: [d][key]; V phase: [key][h]
    __shared__ float Ps [64][64];  // [row][key]

    const int tid = threadIdx.x;
    const int ty = tid >> 4;       // 0..15
    const int tx = tid & 15;       // 0..15
    const int ty4 = ty * 4, tx4 = tx * 4;
    const int b = blockIdx.y;
    const int bx = blockIdx.x;
    // balance: pair heavy/light q-tiles on consecutive blocks
    const int qt = (bx & 1) ? (31 - (bx >> 1)) : (bx >> 1);
    const int qrow0 = qt * 64;
    const float scale = 0.03125f;  // 1/sqrt(1024)

    // Load Q tile transposed: Qs[d][r]
    const float* Qg = g_Q + ((size_t)b * SEQ + qrow0) * HS;
    #pragma unroll
    for (int i = 0; i < 4; i++) {
        int f  = tid + i * 256;   // 0..1023 float4s
        int r  = f >> 4;          // 0..63
        int dq = (f & 15) << 2;   // 0..60
        float4 v = *(const float4*)(Qg + (size_t)r * HS + dq);
        Qs[dq + 0][r] = v.x; Qs[dq + 1][r] = v.y;
        Qs[dq + 2][r] = v.z; Qs[dq + 3][r] = v.w;
    }

    u64 o[4][2];                 // rows i, h-col pairs
    float m[4], l[4];
    #pragma unroll
    for (int i = 0; i < 4; i++) {
        o[i][0] = 0ull; o[i][1] = 0ull;
        m[i] = -1e30f; l[i] = 0.f;
    }

    for (int kt = 0; kt <= qt; kt++) {
        // ---- load K tile transposed: KVs[d][key] ----
        const float* Kg = g_K + ((size_t)b * SEQ + kt * 64) * HS;
        #pragma unroll
        for (int i = 0; i < 4; i++) {
            int f  = tid + i * 256;
            int r  = f >> 4;
            int dq = (f & 15) << 2;
            float4 v = *(const float4*)(Kg + (size_t)r * HS + dq);
            KVs[dq + 0][r] = v.x; KVs[dq + 1][r] = v.y;
            KVs[dq + 2][r] = v.z; KVs[dq + 3][r] = v.w;
        }
        __syncthreads();

        // ---- S = Q K^T (4 rows x 4 keys per thread, keys packed in f32x2) ----
        u64 s2[4][2];
        #pragma unroll
        for (int i = 0; i < 4; i++) { s2[i][0] = 0ull; s2[i][1] = 0ull; }

        #pragma unroll 8
        for (int d = 0; d < HS; d++) {
            float4 q = *(const float4*)&Qs[d][ty4];
            ulonglong2 k2 = *(const ulonglong2*)&KVs[d][tx4];
            u64 q0 = pack2(q.x, q.x), q1 = pack2(q.y, q.y);
            u64 q2 = pack2(q.z, q.z), q3 = pack2(q.w, q.w);
            s2[0][0] = fma2(q0, k2.x, s2[0][0]); s2[0][1] = fma2(q0, k2.y, s2[0][1]);
            s2[1][0] = fma2(q1, k2.x, s2[1][0]); s2[1][1] = fma2(q1, k2.y, s2[1][1]);
            s2[2][0] = fma2(q2, k2.x, s2[2][0]); s2[2][1] = fma2(q2, k2.y, s2[2][1]);
            s2[3][0] = fma2(q3, k2.x, s2[3][0]); s2[3][1] = fma2(q3, k2.y, s2[3][1]);
        }

        float s[4][4];
        #pragma unroll
        for (int i = 0; i < 4; i++) {
            unpack2(s2[i][0], s[i][0], s[i][1]);
            unpack2(s2[i][1], s[i][2], s[i][3]);
            #pragma unroll
            for (int j = 0; j < 4; j++) s[i][j] *= scale;
        }
        if (kt == qt) {  // diagonal tile: causal mask
            #pragma unroll
            for (int i = 0; i < 4; i++)
                #pragma unroll
                for (int j = 0; j < 4; j++)
                    if (tx4 + j > ty4 + i) s[i][j] = -1e30f;
        }

        // ---- online softmax ----
        #pragma unroll
        for (int i = 0; i < 4; i++) {
            float rm = fmaxf(fmaxf(s[i][0], s[i][1]), fmaxf(s[i][2], s[i][3]));
            rm = fmaxf(rm, __shfl_xor_sync(0xffffffffu, rm, 1));
            rm = fmaxf(rm, __shfl_xor_sync(0xffffffffu, rm, 2));
            rm = fmaxf(rm, __shfl_xor_sync(0xffffffffu, rm, 4));
            rm = fmaxf(rm, __shfl_xor_sync(0xffffffffu, rm, 8));
            float mn = fmaxf(m[i], rm);
            float corr = __expf(m[i] - mn);
            m[i] = mn;
            float p0 = __expf(s[i][0] - mn);
            float p1 = __expf(s[i][1] - mn);
            float p2 = __expf(s[i][2] - mn);
            float p3 = __expf(s[i][3] - mn);
            float rs = (p0 + p1) + (p2 + p3);
            rs += __shfl_xor_sync(0xffffffffu, rs, 1);
            rs += __shfl_xor_sync(0xffffffffu, rs, 2);
            rs += __shfl_xor_sync(0xffffffffu, rs, 4);
            rs += __shfl_xor_sync(0xffffffffu, rs, 8);
            l[i] = l[i] * corr + rs;
            u64 c2 = pack2(corr, corr);
            o[i][0] = mul2(o[i][0], c2);
            o[i][1] = mul2(o[i][1], c2);
            Ps[ty4 + i][tx4 + 0] = p0;
            Ps[ty4 + i][tx4 + 1] = p1;
            Ps[ty4 + i][tx4 + 2] = p2;
            Ps[ty4 + i][tx4 + 3] = p3;
        }
        __syncthreads();   // all K reads + P writes done

        // ---- load V tile (natural layout) into the shared KV buffer ----
        const float* Vg = g_V + ((size_t)b * SEQ + kt * 64) * HS;
        #pragma unroll
        for (int i = 0; i < 4; i++) {
            int f  = tid + i * 256;
            int r  = f >> 4;
            int dq = (f & 15) << 2;
            *(float4*)&KVs[r][dq] = *(const float4*)(Vg + (size_t)r * HS + dq);
        }
        __syncthreads();   // V + P visible

        // ---- O += P @ V ----
        #pragma unroll 8
        for (int k = 0; k < 64; k++) {
            ulonglong2 vv = *(const ulonglong2*)&KVs[k][tx4];
            #pragma unroll
            for (int i = 0; i < 4; i++) {
                float pv = Ps[ty4 + i][k];
                u64 p2v = pack2(pv, pv);
                o[i][0] = fma2(p2v, vv.x, o[i][0]);
                o[i][1] = fma2(p2v, vv.y, o[i][1]);
            }
        }
        __syncthreads();   // done with V before next K overwrite
    }

    // ---- epilogue: normalize and store ----
    #pragma unroll
    for (int i = 0; i < 4; i++) {
        float inv = 1.0f / l[i];
        float a0, a1, a2, a3;
        unpack2(o[i][0], a0, a1);
        unpack2(o[i][1], a2, a3);
        *(float4*)(out + ((size_t)b * SEQ + qrow0 + ty4 + i) * HS + tx4) =
            make_float4(a0 * inv, a1 * inv, a2 * inv, a3 * inv);
    }
}

extern "C" void kernel_launch(void* const* d_in, const int* in_sizes, int n_in,
                              void* d_out, int out_size)
{
    (void)in_sizes; (void)n_in; (void)out_size;
    const float* index  = (const float*)d_in[0];
    const float* memory = (const float*)d_in[1];
    const float* Wq     = (const float*)d_in[2];
    const float* Wk     = (const float*)d_in[3];
    const float* Wv     = (const float*)d_in[4];
    float* out = (float*)d_out;

    proj_kernel<<<dim3(MROWS / 128, 3), 256>>>(index, memory, Wq, Wk, Wv);
    attn_kernel<<<dim3(SEQ / 64, BATCH), 256>>>(out);
}

// round 3
// speedup vs baseline: 1.1453x; 1.1453x over previous
#include <cuda_runtime.h>

#define BATCH 8
#define SEQ   2048
#define EMB   1024
#define HS    64
#define MROWS (BATCH*SEQ)   // 16384

typedef unsigned long long u64;

// Projections. Q,K stored TRANSPOSED: layout [b*64 + d][t] (t in 0..2047). V natural.
__device__ float g_Qt[(size_t)MROWS * HS];
__device__ float g_Kt[(size_t)MROWS * HS];
__device__ float g_V [(size_t)MROWS * HS];

// Work balance: SM hosting block bid also gets bid+148 => bx pairs with (bx+20)%32.
// This map makes each pair's (qt+1) sums land in 30..34 (ideal 33).
__device__ const int qt_map[32] = {
    0,4,8,12,29,25,21,17,1,5,9,13,28,24,20,16,
    2,6,10,14,31,27,23,19,3,7,11,15,30,26,22,18};

// ---- packed f32x2 helpers (Blackwell FFMA2; ptxas never emits these from C++) ----
__device__ __forceinline__ u64 pack2(float x, float y) {
    u64 r; asm("mov.b64 %0, {%1, %2};" : "=l"(r) : "f"(x), "f"(y)); return r;
}
__device__ __forceinline__ void unpack2(u64 a, float& x, float& y) {
    asm("mov.b64 {%0, %1}, %2;" : "=f"(x), "=f"(y) : "l"(a));
}
__device__ __forceinline__ u64 fma2(u64 a, u64 b, u64 c) {
    u64 d; asm("fma.rn.f32x2 %0, %1, %2, %3;" : "=l"(d) : "l"(a), "l"(b), "l"(c)); return d;
}
__device__ __forceinline__ u64 mul2(u64 a, u64 b) {
    u64 d; asm("mul.rn.f32x2 %0, %1, %2;" : "=l"(d) : "l"(a), "l"(b)); return d;
}

// ============================================================================
// Projection GEMM: Y[M,64] = X[M,1024] @ W[1024,64]
// which: 0 -> Qt (transposed store), 1 -> Kt (transposed), 2 -> V (natural)
// Tile 128x64, BK=16, double-buffered smem with register prefetch.
// Thread (ty,tx): 8 rows (4 fp32x2 row-pairs) x 4 cols.
// ============================================================================
__global__ __launch_bounds__(256, 3) void proj_kernel(
    const float* __restrict__ Xq, const float* __restrict__ Xkv,
    const float* __restrict__ Wq, const float* __restrict__ Wk,
    const float* __restrict__ Wv)
{
    __shared__ float As[2][16][132];  // [k][row] transposed
    __shared__ float Bs[2][16][64];   // [k][col]

    const int tid = threadIdx.x;
    const int which = blockIdx.y;
    const float* X = (which == 0) ? Xq : Xkv;
    const float* W = (which == 0) ? Wq : ((which == 1) ? Wk : Wv);

    const int row0 = blockIdx.x * 128;
    const int ty8 = (tid >> 4) * 8;
    const int tx4 = (tid & 15) * 4;

    const int lr  = tid >> 2;           // A row within tile (two loads: +0, +64)
    const int lkq = (tid & 3) << 2;     // A k offset 0,4,8,12
    const int bkk = tid >> 4;           // B k row
    const int bc4 = (tid & 15) << 2;    // B col

    u64 acc[4][4];
    #pragma unroll
    for (int i = 0; i < 4; i++)
        #pragma unroll
        for (int j = 0; j < 4; j++) acc[i][j] = 0ull;

    float4 a_reg[2], b_reg;
    #pragma unroll
    for (int i = 0; i < 2; i++)
        a_reg[i] = *(const float4*)(X + (size_t)(row0 + lr + i * 64) * EMB + lkq);
    b_reg = *(const float4*)(W + (size_t)bkk * HS + bc4);
    #pragma unroll
    for (int i = 0; i < 2; i++) {
        As[0][lkq + 0][lr + i * 64] = a_reg[i].x;
        As[0][lkq + 1][lr + i * 64] = a_reg[i].y;
        As[0][lkq + 2][lr + i * 64] = a_reg[i].z;
        As[0][lkq + 3][lr + i * 64] = a_reg[i].w;
    }
    *(float4*)&Bs[0][bkk][bc4] = b_reg;
    __syncthreads();

    for (int t = 0; t < 64; t++) {
        const int s = t & 1;
        if (t < 63) {
            const int k0 = (t + 1) * 16;
            #pragma unroll
            for (int i = 0; i < 2; i++)
                a_reg[i] = *(const float4*)(X + (size_t)(row0 + lr + i * 64) * EMB + k0 + lkq);
            b_reg = *(const float4*)(W + (size_t)(k0 + bkk) * HS + bc4);
        }

        #pragma unroll
        for (int kk = 0; kk < 16; kk++) {
            ulonglong2 a01 = *(const ulonglong2*)&As[s][kk][ty8];
            ulonglong2 a23 = *(const ulonglong2*)&As[s][kk][ty8 + 4];
            float4 b = *(const float4*)&Bs[s][kk][tx4];
            u64 bs0 = pack2(b.x, b.x), bs1 = pack2(b.y, b.y);
            u64 bs2 = pack2(b.z, b.z), bs3 = pack2(b.w, b.w);
            acc[0][0] = fma2(a01.x, bs0, acc[0][0]);
            acc[0][1] = fma2(a01.x, bs1, acc[0][1]);
            acc[0][2] = fma2(a01.x, bs2, acc[0][2]);
            acc[0][3] = fma2(a01.x, bs3, acc[0][3]);
            acc[1][0] = fma2(a01.y, bs0, acc[1][0]);
            acc[1][1] = fma2(a01.y, bs1, acc[1][1]);
            acc[1][2] = fma2(a01.y, bs2, acc[1][2]);
            acc[1][3] = fma2(a01.y, bs3, acc[1][3]);
            acc[2][0] = fma2(a23.x, bs0, acc[2][0]);
            acc[2][1] = fma2(a23.x, bs1, acc[2][1]);
            acc[2][2] = fma2(a23.x, bs2, acc[2][2]);
            acc[2][3] = fma2(a23.x, bs3, acc[2][3]);
            acc[3][0] = fma2(a23.y, bs0, acc[3][0]);
            acc[3][1] = fma2(a23.y, bs1, acc[3][1]);
            acc[3][2] = fma2(a23.y, bs2, acc[3][2]);
            acc[3][3] = fma2(a23.y, bs3, acc[3][3]);
        }

        if (t < 63) {
            const int d = s ^ 1;
            #pragma unroll
            for (int i = 0; i < 2; i++) {
                As[d][lkq + 0][lr + i * 64] = a_reg[i].x;
                As[d][lkq + 1][lr + i * 64] = a_reg[i].y;
                As[d][lkq + 2][lr + i * 64] = a_reg[i].z;
                As[d][lkq + 3][lr + i * 64] = a_reg[i].w;
            }
            *(float4*)&Bs[d][bkk][bc4] = b_reg;
        }
        __syncthreads();
    }

    if (which == 2) {  // V: natural [t][h]
        #pragma unroll
        for (int i = 0; i < 4; i++) {
            float r0v[4], r1v[4];
            #pragma unroll
            for (int j = 0; j < 4; j++) unpack2(acc[i][j], r0v[j], r1v[j]);
            *(float4*)(g_V + (size_t)(row0 + ty8 + 2 * i)     * HS + tx4) =
                make_float4(r0v[0], r0v[1], r0v[2], r0v[3]);
            *(float4*)(g_V + (size_t)(row0 + ty8 + 2 * i + 1) * HS + tx4) =
                make_float4(r1v[0], r1v[1], r1v[2], r1v[3]);
        }
    } else {           // Q,K: transposed [b*64+h][t], row pair -> one STG.64
        float* T = (which == 0) ? g_Qt : g_Kt;
        const int b  = (row0 >> 11);
        const int tt = (row0 & 2047) + ty8;
        #pragma unroll
        for (int i = 0; i < 4; i++)
            #pragma unroll
            for (int j = 0; j < 4; j++)
                *(u64*)(T + (size_t)(b * 64 + tx4 + j) * SEQ + tt + 2 * i) = acc[i][j];
    }
}

// ============================================================================
// Flash attention (causal). Block = one 64-row q-tile of one batch, 256 thr.
// Smem: Qs[d][r] (loaded once), KB[d][key] -> overlaid by P[r][k], VB[k][h].
// All fills are straight coalesced copies (sources pre-transposed).
// Thread (ty,tx): 4 q-rows x 4 keys / 4 h-cols.
// ============================================================================
__global__ __launch_bounds__(256, 2) void attn_kernel(float* __restrict__ out)
{
    __shared__ float Qs[64 * 64];
    __shared__ float KB[64 * 64];   // K phase: [d][key]; P phase: [row][key]
    __shared__ float VB[64 * 64];   // [key][h]

    const int tid = threadIdx.x;
    const int ty4 = (tid >> 4) * 4;
    const int tx4 = (tid & 15) * 4;
    const int b = blockIdx.y;
    const int qt = qt_map[blockIdx.x];
    const int qrow0 = qt * 64;
    const float scale = 0.03125f;   // 1/sqrt(1024)

    const int dd = tid >> 4;        // loader row (4 chunks of 16)
    const int c4 = (tid & 15) << 2; // loader col

    // Q once: straight copy from g_Qt
    const float* Qg = g_Qt + (size_t)(b * 64) * SEQ + qrow0;
    #pragma unroll
    for (int i = 0; i < 4; i++) {
        int d = dd + i * 16;
        *(float4*)&Qs[d * 64 + c4] = *(const float4*)(Qg + (size_t)d * SEQ + c4);
    }

    u64 o[4][2];
    float m[4], l[4];
    #pragma unroll
    for (int i = 0; i < 4; i++) {
        o[i][0] = 0ull; o[i][1] = 0ull;
        m[i] = -1e30f; l[i] = 0.f;
    }

    const float* Kg = g_Kt + (size_t)(b * 64) * SEQ;
    const float* Vg = g_V  + (size_t)b * SEQ * HS;

    for (int kt = 0; kt <= qt; kt++) {
        __syncthreads();   // prev PV finished reading P (KB) and V (VB)

        // K tile (straight copy) + V tile (natural copy); LDGs overlap
        #pragma unroll
        for (int i = 0; i < 4; i++) {
            int d = dd + i * 16;
            *(float4*)&KB[d * 64 + c4] =
                *(const float4*)(Kg + (size_t)d * SEQ + kt * 64 + c4);
            *(float4*)&VB[d * 64 + c4] =
                *(const float4*)(Vg + (size_t)(kt * 64 + d) * HS + c4);
        }
        __syncthreads();

        // ---- S = Q K^T ----
        u64 s2[4][2];
        #pragma unroll
        for (int i = 0; i < 4; i++) { s2[i][0] = 0ull; s2[i][1] = 0ull; }

        #pragma unroll 8
        for (int d = 0; d < HS; d++) {
            float4 q = *(const float4*)&Qs[d * 64 + ty4];
            ulonglong2 k2 = *(const ulonglong2*)&KB[d * 64 + tx4];
            u64 q0 = pack2(q.x, q.x), q1 = pack2(q.y, q.y);
            u64 q2 = pack2(q.z, q.z), q3 = pack2(q.w, q.w);
            s2[0][0] = fma2(q0, k2.x, s2[0][0]); s2[0][1] = fma2(q0, k2.y, s2[0][1]);
            s2[1][0] = fma2(q1, k2.x, s2[1][0]); s2[1][1] = fma2(q1, k2.y, s2[1][1]);
            s2[2][0] = fma2(q2, k2.x, s2[2][0]); s2[2][1] = fma2(q2, k2.y, s2[2][1]);
            s2[3][0] = fma2(q3, k2.x, s2[3][0]); s2[3][1] = fma2(q3, k2.y, s2[3][1]);
        }

        float s[4][4];
        #pragma unroll
        for (int i = 0; i < 4; i++) {
            unpack2(s2[i][0], s[i][0], s[i][1]);
            unpack2(s2[i][1], s[i][2], s[i][3]);
            #pragma unroll
            for (int j = 0; j < 4; j++) s[i][j] *= scale;
        }
        if (kt == qt) {
            #pragma unroll
            for (int i = 0; i < 4; i++)
                #pragma unroll
                for (int j = 0; j < 4; j++)
                    if (tx4 + j > ty4 + i) s[i][j] = -1e30f;
        }

        // ---- online softmax ----
        float p[4][4];
        #pragma unroll
        for (int i = 0; i < 4; i++) {
            float rm = fmaxf(fmaxf(s[i][0], s[i][1]), fmaxf(s[i][2], s[i][3]));
            rm = fmaxf(rm, __shfl_xor_sync(0xffffffffu, rm, 1));
            rm = fmaxf(rm, __shfl_xor_sync(0xffffffffu, rm, 2));
            rm = fmaxf(rm, __shfl_xor_sync(0xffffffffu, rm, 4));
            rm = fmaxf(rm, __shfl_xor_sync(0xffffffffu, rm, 8));
            float mn = fmaxf(m[i], rm);
            float corr = __expf(m[i] - mn);
            m[i] = mn;
            p[i][0] = __expf(s[i][0] - mn);
            p[i][1] = __expf(s[i][1] - mn);
            p[i][2] = __expf(s[i][2] - mn);
            p[i][3] = __expf(s[i][3] - mn);
            float rs = (p[i][0] + p[i][1]) + (p[i][2] + p[i][3]);
            rs += __shfl_xor_sync(0xffffffffu, rs, 1);
            rs += __shfl_xor_sync(0xffffffffu, rs, 2);
            rs += __shfl_xor_sync(0xffffffffu, rs, 4);
            rs += __shfl_xor_sync(0xffffffffu, rs, 8);
            l[i] = l[i] * corr + rs;
            u64 c2 = pack2(corr, corr);
            o[i][0] = mul2(o[i][0], c2);
            o[i][1] = mul2(o[i][1], c2);
        }
        __syncthreads();   // all K reads done -> KB reusable for P

        #pragma unroll
        for (int i = 0; i < 4; i++)
            *(float4*)&KB[(ty4 + i) * 64 + tx4] =
                make_float4(p[i][0], p[i][1], p[i][2], p[i][3]);
        __syncthreads();   // P visible

        // ---- O += P @ V ----
        #pragma unroll 2
        for (int k0 = 0; k0 < 64; k0 += 4) {
            float4 pr[4];
            #pragma unroll
            for (int i = 0; i < 4; i++)
                pr[i] = *(const float4*)&KB[(ty4 + i) * 64 + k0];
            ulonglong2 v0 = *(const ulonglong2*)&VB[(k0 + 0) * 64 + tx4];
            ulonglong2 v1 = *(const ulonglong2*)&VB[(k0 + 1) * 64 + tx4];
            ulonglong2 v2 = *(const ulonglong2*)&VB[(k0 + 2) * 64 + tx4];
            ulonglong2 v3 = *(const ulonglong2*)&VB[(k0 + 3) * 64 + tx4];
            #pragma unroll
            for (int i = 0; i < 4; i++) {
                u64 pa = pack2(pr[i].x, pr[i].x);
                o[i][0] = fma2(pa, v0.x, o[i][0]); o[i][1] = fma2(pa, v0.y, o[i][1]);
                u64 pb = pack2(pr[i].y, pr[i].y);
                o[i][0] = fma2(pb, v1.x, o[i][0]); o[i][1] = fma2(pb, v1.y, o[i][1]);
                u64 pc = pack2(pr[i].z, pr[i].z);
                o[i][0] = fma2(pc, v2.x, o[i][0]); o[i][1] = fma2(pc, v2.y, o[i][1]);
                u64 pd = pack2(pr[i].w, pr[i].w);
                o[i][0] = fma2(pd, v3.x, o[i][0]); o[i][1] = fma2(pd, v3.y, o[i][1]);
            }
        }
    }

    #pragma unroll
    for (int i = 0; i < 4; i++) {
        float inv = 1.0f / l[i];
        float a0, a1, a2, a3;
        unpack2(o[i][0], a0, a1);
        unpack2(o[i][1], a2, a3);
        *(float4*)(out + ((size_t)b * SEQ + qrow0 + ty4 + i) * HS + tx4) =
            make_float4(a0 * inv, a1 * inv, a2 * inv, a3 * inv);
    }
}

extern "C" void kernel_launch(void* const* d_in, const int* in_sizes, int n_in,
                              void* d_out, int out_size)
{
    (void)in_sizes; (void)n_in; (void)out_size;
    const float* index  = (const float*)d_in[0];
    const float* memory = (const float*)d_in[1];
    const float* Wq     = (const float*)d_in[2];
    const float* Wk     = (const float*)d_in[3];
    const float* Wv     = (const float*)d_in[4];
    float* out = (float*)d_out;

    proj_kernel<<<dim3(MROWS / 128, 3), 256>>>(index, memory, Wq, Wk, Wv);
    attn_kernel<<<dim3(SEQ / 64, BATCH), 256>>>(out);
}

// round 4
// speedup vs baseline: 1.3674x; 1.1940x over previous
#include <cuda_runtime.h>

#define BATCH 8
#define SEQ   2048
#define EMB   1024
#define HS    64
#define MROWS (BATCH*SEQ)

typedef unsigned long long u64;
typedef unsigned int u32;

// Q,K stored TRANSPOSED [b*64+d][t] and pre-rounded to tf32; V natural fp32.
__device__ float g_Qt[(size_t)MROWS * HS];
__device__ float g_Kt[(size_t)MROWS * HS];
__device__ float g_V [(size_t)MROWS * HS];

__device__ const int qt_map[32] = {
    0,4,8,12,29,25,21,17,1,5,9,13,28,24,20,16,
    2,6,10,14,31,27,23,19,3,7,11,15,30,26,22,18};

__device__ __forceinline__ u64 pack2(float x, float y) {
    u64 r; asm("mov.b64 %0, {%1, %2};" : "=l"(r) : "f"(x), "f"(y)); return r;
}
__device__ __forceinline__ void unpack2(u64 a, float& x, float& y) {
    asm("mov.b64 {%0, %1}, %2;" : "=f"(x), "=f"(y) : "l"(a));
}
__device__ __forceinline__ u64 fma2(u64 a, u64 b, u64 c) {
    u64 d; asm("fma.rn.f32x2 %0, %1, %2, %3;" : "=l"(d) : "l"(a), "l"(b), "l"(c)); return d;
}
__device__ __forceinline__ u64 mul2(u64 a, u64 b) {
    u64 d; asm("mul.rn.f32x2 %0, %1, %2;" : "=l"(d) : "l"(a), "l"(b)); return d;
}
__device__ __forceinline__ u32 tf32r(float x) {
    u32 r; asm("cvt.rna.tf32.f32 %0, %1;" : "=r"(r) : "f"(x)); return r;
}
__device__ __forceinline__ u64 pack2u(u32 lo, u32 hi) {
    u64 r; asm("mov.b64 %0, {%1, %2};" : "=l"(r) : "r"(lo), "r"(hi)); return r;
}
__device__ __forceinline__ void mma8(float* c, u32 a0, u32 a1, u32 a2, u32 a3,
                                     u32 b0, u32 b1) {
    asm volatile(
        "mma.sync.aligned.m16n8k8.row.col.f32.tf32.tf32.f32 "
        "{%0,%1,%2,%3}, {%4,%5,%6,%7}, {%8,%9}, {%0,%1,%2,%3};"
        : "+f"(c[0]), "+f"(c[1]), "+f"(c[2]), "+f"(c[3])
        : "r"(a0), "r"(a1), "r"(a2), "r"(a3), "r"(b0), "r"(b1));
}

// ============================================================================
// Projection GEMM (fp32 FFMA2, double-buffered). Q/K epilogues round to tf32.
// ============================================================================
__global__ __launch_bounds__(256, 3) void proj_kernel(
    const float* __restrict__ Xq, const float* __restrict__ Xkv,
    const float* __restrict__ Wq, const float* __restrict__ Wk,
    const float* __restrict__ Wv)
{
    __shared__ float As[2][16][132];
    __shared__ float Bs[2][16][64];

    const int tid = threadIdx.x;
    const int which = blockIdx.y;
    const float* X = (which == 0) ? Xq : Xkv;
    const float* W = (which == 0) ? Wq : ((which == 1) ? Wk : Wv);

    const int row0 = blockIdx.x * 128;
    const int ty8 = (tid >> 4) * 8;
    const int tx4 = (tid & 15) * 4;
    const int lr  = tid >> 2;
    const int lkq = (tid & 3) << 2;
    const int bkk = tid >> 4;
    const int bc4 = (tid & 15) << 2;

    u64 acc[4][4];
    #pragma unroll
    for (int i = 0; i < 4; i++)
        #pragma unroll
        for (int j = 0; j < 4; j++) acc[i][j] = 0ull;

    float4 a_reg[2], b_reg;
    #pragma unroll
    for (int i = 0; i < 2; i++)
        a_reg[i] = *(const float4*)(X + (size_t)(row0 + lr + i * 64) * EMB + lkq);
    b_reg = *(const float4*)(W + (size_t)bkk * HS + bc4);
    #pragma unroll
    for (int i = 0; i < 2; i++) {
        As[0][lkq + 0][lr + i * 64] = a_reg[i].x;
        As[0][lkq + 1][lr + i * 64] = a_reg[i].y;
        As[0][lkq + 2][lr + i * 64] = a_reg[i].z;
        As[0][lkq + 3][lr + i * 64] = a_reg[i].w;
    }
    *(float4*)&Bs[0][bkk][bc4] = b_reg;
    __syncthreads();

    for (int t = 0; t < 64; t++) {
        const int s = t & 1;
        if (t < 63) {
            const int k0 = (t + 1) * 16;
            #pragma unroll
            for (int i = 0; i < 2; i++)
                a_reg[i] = *(const float4*)(X + (size_t)(row0 + lr + i * 64) * EMB + k0 + lkq);
            b_reg = *(const float4*)(W + (size_t)(k0 + bkk) * HS + bc4);
        }
        #pragma unroll
        for (int kk = 0; kk < 16; kk++) {
            ulonglong2 a01 = *(const ulonglong2*)&As[s][kk][ty8];
            ulonglong2 a23 = *(const ulonglong2*)&As[s][kk][ty8 + 4];
            float4 b = *(const float4*)&Bs[s][kk][tx4];
            u64 bs0 = pack2(b.x, b.x), bs1 = pack2(b.y, b.y);
            u64 bs2 = pack2(b.z, b.z), bs3 = pack2(b.w, b.w);
            acc[0][0] = fma2(a01.x, bs0, acc[0][0]);
            acc[0][1] = fma2(a01.x, bs1, acc[0][1]);
            acc[0][2] = fma2(a01.x, bs2, acc[0][2]);
            acc[0][3] = fma2(a01.x, bs3, acc[0][3]);
            acc[1][0] = fma2(a01.y, bs0, acc[1][0]);
            acc[1][1] = fma2(a01.y, bs1, acc[1][1]);
            acc[1][2] = fma2(a01.y, bs2, acc[1][2]);
            acc[1][3] = fma2(a01.y, bs3, acc[1][3]);
            acc[2][0] = fma2(a23.x, bs0, acc[2][0]);
            acc[2][1] = fma2(a23.x, bs1, acc[2][1]);
            acc[2][2] = fma2(a23.x, bs2, acc[2][2]);
            acc[2][3] = fma2(a23.x, bs3, acc[2][3]);
            acc[3][0] = fma2(a23.y, bs0, acc[3][0]);
            acc[3][1] = fma2(a23.y, bs1, acc[3][1]);
            acc[3][2] = fma2(a23.y, bs2, acc[3][2]);
            acc[3][3] = fma2(a23.y, bs3, acc[3][3]);
        }
        if (t < 63) {
            const int d = s ^ 1;
            #pragma unroll
            for (int i = 0; i < 2; i++) {
                As[d][lkq + 0][lr + i * 64] = a_reg[i].x;
                As[d][lkq + 1][lr + i * 64] = a_reg[i].y;
                As[d][lkq + 2][lr + i * 64] = a_reg[i].z;
                As[d][lkq + 3][lr + i * 64] = a_reg[i].w;
            }
            *(float4*)&Bs[d][bkk][bc4] = b_reg;
        }
        __syncthreads();
    }

    if (which == 2) {
        #pragma unroll
        for (int i = 0; i < 4; i++) {
            float r0v[4], r1v[4];
            #pragma unroll
            for (int j = 0; j < 4; j++) unpack2(acc[i][j], r0v[j], r1v[j]);
            *(float4*)(g_V + (size_t)(row0 + ty8 + 2 * i)     * HS + tx4) =
                make_float4(r0v[0], r0v[1], r0v[2], r0v[3]);
            *(float4*)(g_V + (size_t)(row0 + ty8 + 2 * i + 1) * HS + tx4) =
                make_float4(r1v[0], r1v[1], r1v[2], r1v[3]);
        }
    } else {
        float* T = (which == 0) ? g_Qt : g_Kt;
        const int b  = (row0 >> 11);
        const int tt = (row0 & 2047) + ty8;
        #pragma unroll
        for (int i = 0; i < 4; i++)
            #pragma unroll
            for (int j = 0; j < 4; j++) {
                float lo, hi; unpack2(acc[i][j], lo, hi);
                *(u64*)(T + (size_t)(b * 64 + tx4 + j) * SEQ + tt + 2 * i) =
                    pack2u(tf32r(lo), tf32r(hi));
            }
    }
}

// ============================================================================
// Flash attention: QK on tensor pipe (tf32 mma, warps 0-3), PV fp32 FFMA2.
// Dynamic smem (floats): QS[64*72] KS[64*72] PS[64*68] VS[64*72] NM[64] NS[64]
// ============================================================================
#define OFF_QS 0
#define OFF_KS 4608
#define OFF_PS 9216
#define OFF_VS 13568
#define OFF_NM 18176
#define OFF_NS 18240
#define SMEM_FLOATS 18304

__global__ __launch_bounds__(256, 2) void attn_kernel(float* __restrict__ out)
{
    extern __shared__ float sm[];
    float* QS = sm + OFF_QS;
    float* KS = sm + OFF_KS;
    float* PS = sm + OFF_PS;
    float* VS = sm + OFF_VS;
    float* NM = sm + OFF_NM;
    float* NS = sm + OFF_NS;

    const int tid  = threadIdx.x;
    const int wid  = tid >> 5;
    const int lane = tid & 31;
    const int grp  = lane >> 2;     // lane/4
    const int t4   = lane & 3;      // lane%4
    const int ty4  = (tid >> 4) * 4;
    const int tx4  = (tid & 15) * 4;
    const int dd   = tid >> 4;      // fill row base
    const int c4   = (tid & 15) << 2;

    const int b = blockIdx.y;
    const int qt = qt_map[blockIdx.x];
    const int qrow0 = qt * 64;
    const float scale = 0.03125f;

    const float* Qg = g_Qt + (size_t)(b * 64) * SEQ + qrow0;
    const float* Kg = g_Kt + (size_t)(b * 64) * SEQ;
    const float* Vg = g_V  + (size_t)b * SEQ * HS;

    // stage Q (tf32 bits) as QS[d][r], stride 72
    #pragma unroll
    for (int i = 0; i < 4; i++) {
        int d = dd + i * 16;
        *(float4*)&QS[d * 72 + c4] = *(const float4*)(Qg + (size_t)d * SEQ + c4);
    }

    u64 o[4][2];
    float m[4], l[4];
    #pragma unroll
    for (int i = 0; i < 4; i++) {
        o[i][0] = 0ull; o[i][1] = 0ull; m[i] = -1e30f; l[i] = 0.f;
    }
    float mq0 = -1e30f, mq1 = -1e30f;   // QK-warp row-max state
    const int r0 = ((wid & 3) << 4) + grp;

    for (int kt = 0; kt <= qt; kt++) {
        __syncthreads();   // prior PV done with PS/VS/NM/NS; prior QK done with KS

        #pragma unroll
        for (int i = 0; i < 4; i++) {
            int d = dd + i * 16;
            *(float4*)&KS[d * 72 + c4] =
                *(const float4*)(Kg + (size_t)d * SEQ + kt * 64 + c4);
            *(float4*)&VS[d * 72 + c4] =
                *(const float4*)(Vg + (size_t)(kt * 64 + d) * HS + c4);
        }
        __syncthreads();

        if (wid < 4) {
            float S[8][4];
            #pragma unroll
            for (int nb = 0; nb < 8; nb++)
                #pragma unroll
                for (int j = 0; j < 4; j++) S[nb][j] = 0.f;

            #pragma unroll
            for (int kk = 0; kk < 8; kk++) {
                const int d0 = kk * 8;
                u32 a0 = __float_as_uint(QS[(d0 + t4)     * 72 + r0]);
                u32 a1 = __float_as_uint(QS[(d0 + t4)     * 72 + r0 + 8]);
                u32 a2 = __float_as_uint(QS[(d0 + t4 + 4) * 72 + r0]);
                u32 a3 = __float_as_uint(QS[(d0 + t4 + 4) * 72 + r0 + 8]);
                #pragma unroll
                for (int nb = 0; nb < 8; nb++) {
                    u32 b0 = __float_as_uint(KS[(d0 + t4)     * 72 + nb * 8 + grp]);
                    u32 b1 = __float_as_uint(KS[(d0 + t4 + 4) * 72 + nb * 8 + grp]);
                    mma8(S[nb], a0, a1, a2, a3, b0, b1);
                }
            }

            #pragma unroll
            for (int nb = 0; nb < 8; nb++)
                #pragma unroll
                for (int j = 0; j < 4; j++) S[nb][j] *= scale;

            if (kt == qt) {  // causal mask on diagonal tile
                #pragma unroll
                for (int nb = 0; nb < 8; nb++) {
                    int c0 = nb * 8 + 2 * t4;
                    if (c0     > r0)     S[nb][0] = -1e30f;
                    if (c0 + 1 > r0)     S[nb][1] = -1e30f;
                    if (c0     > r0 + 8) S[nb][2] = -1e30f;
                    if (c0 + 1 > r0 + 8) S[nb][3] = -1e30f;
                }
            }

            float mx0 = -1e30f, mx1 = -1e30f;
            #pragma unroll
            for (int nb = 0; nb < 8; nb++) {
                mx0 = fmaxf(mx0, fmaxf(S[nb][0], S[nb][1]));
                mx1 = fmaxf(mx1, fmaxf(S[nb][2], S[nb][3]));
            }
            mx0 = fmaxf(mx0, __shfl_xor_sync(0xffffffffu, mx0, 1));
            mx0 = fmaxf(mx0, __shfl_xor_sync(0xffffffffu, mx0, 2));
            mx1 = fmaxf(mx1, __shfl_xor_sync(0xffffffffu, mx1, 1));
            mx1 = fmaxf(mx1, __shfl_xor_sync(0xffffffffu, mx1, 2));
            const float gm0 = fmaxf(mq0, mx0);
            const float gm1 = fmaxf(mq1, mx1);
            mq0 = gm0; mq1 = gm1;

            float s0 = 0.f, s1 = 0.f;
            #pragma unroll
            for (int nb = 0; nb < 8; nb++) {
                float p0 = __expf(S[nb][0] - gm0);
                float p1 = __expf(S[nb][1] - gm0);
                float p2 = __expf(S[nb][2] - gm1);
                float p3 = __expf(S[nb][3] - gm1);
                s0 += p0 + p1; s1 += p2 + p3;
                *(u64*)&PS[r0 * 68 + nb * 8 + 2 * t4]       = pack2(p0, p1);
                *(u64*)&PS[(r0 + 8) * 68 + nb * 8 + 2 * t4] = pack2(p2, p3);
            }
            s0 += __shfl_xor_sync(0xffffffffu, s0, 1);
            s0 += __shfl_xor_sync(0xffffffffu, s0, 2);
            s1 += __shfl_xor_sync(0xffffffffu, s1, 1);
            s1 += __shfl_xor_sync(0xffffffffu, s1, 2);
            if (t4 == 0) {
                NM[r0] = gm0; NM[r0 + 8] = gm1;
                NS[r0] = s0;  NS[r0 + 8] = s1;
            }
        }
        __syncthreads();   // P/NM/NS visible

        // ---- rescale state, O += P @ V (fp32 FFMA2) ----
        #pragma unroll
        for (int i = 0; i < 4; i++) {
            float mn = NM[ty4 + i];
            float corr = __expf(m[i] - mn);
            m[i] = mn;
            l[i] = l[i] * corr + NS[ty4 + i];
            u64 c2 = pack2(corr, corr);
            o[i][0] = mul2(o[i][0], c2);
            o[i][1] = mul2(o[i][1], c2);
        }
        #pragma unroll 2
        for (int k0 = 0; k0 < 64; k0 += 4) {
            float4 pr[4];
            #pragma unroll
            for (int i = 0; i < 4; i++)
                pr[i] = *(const float4*)&PS[(ty4 + i) * 68 + k0];
            ulonglong2 v0 = *(const ulonglong2*)&VS[(k0 + 0) * 72 + tx4];
            ulonglong2 v1 = *(const ulonglong2*)&VS[(k0 + 1) * 72 + tx4];
            ulonglong2 v2 = *(const ulonglong2*)&VS[(k0 + 2) * 72 + tx4];
            ulonglong2 v3 = *(const ulonglong2*)&VS[(k0 + 3) * 72 + tx4];
            #pragma unroll
            for (int i = 0; i < 4; i++) {
                u64 pa = pack2(pr[i].x, pr[i].x);
                o[i][0] = fma2(pa, v0.x, o[i][0]); o[i][1] = fma2(pa, v0.y, o[i][1]);
                u64 pb = pack2(pr[i].y, pr[i].y);
                o[i][0] = fma2(pb, v1.x, o[i][0]); o[i][1] = fma2(pb, v1.y, o[i][1]);
                u64 pc = pack2(pr[i].z, pr[i].z);
                o[i][0] = fma2(pc, v2.x, o[i][0]); o[i][1] = fma2(pc, v2.y, o[i][1]);
                u64 pd = pack2(pr[i].w, pr[i].w);
                o[i][0] = fma2(pd, v3.x, o[i][0]); o[i][1] = fma2(pd, v3.y, o[i][1]);
            }
        }
    }

    #pragma unroll
    for (int i = 0; i < 4; i++) {
        float inv = 1.0f / l[i];
        float a0, a1, a2, a3;
        unpack2(o[i][0], a0, a1);
        unpack2(o[i][1], a2, a3);
        *(float4*)(out + ((size_t)b * SEQ + qrow0 + ty4 + i) * HS + tx4) =
            make_float4(a0 * inv, a1 * inv, a2 * inv, a3 * inv);
    }
}

extern "C" void kernel_launch(void* const* d_in, const int* in_sizes, int n_in,
                              void* d_out, int out_size)
{
    (void)in_sizes; (void)n_in; (void)out_size;
    const float* index  = (const float*)d_in[0];
    const float* memory = (const float*)d_in[1];
    const float* Wq     = (const float*)d_in[2];
    const float* Wk     = (const float*)d_in[3];
    const float* Wv     = (const float*)d_in[4];
    float* out = (float*)d_out;

    cudaFuncSetAttribute(attn_kernel,
                         cudaFuncAttributeMaxDynamicSharedMemorySize,
                         SMEM_FLOATS * 4);

    proj_kernel<<<dim3(MROWS / 128, 3), 256>>>(index, memory, Wq, Wk, Wv);
    attn_kernel<<<dim3(SEQ / 64, BATCH), 256, SMEM_FLOATS * 4>>>(out);
}

// round 5
// speedup vs baseline: 2.1835x; 1.5968x over previous
#include <cuda_runtime.h>

#define BATCH 8
#define SEQ   2048
#define EMB   1024
#define HS    64
#define MROWS (BATCH*SEQ)

typedef unsigned long long u64;
typedef unsigned int u32;

// Q, K, V all stored TRANSPOSED [b*64+d][t], values pre-rounded to tf32.
__device__ float g_Qt[(size_t)MROWS * HS];
__device__ float g_Kt[(size_t)MROWS * HS];
__device__ float g_Vt[(size_t)MROWS * HS];

__device__ const int qt_map[32] = {
    0,4,8,12,29,25,21,17,1,5,9,13,28,24,20,16,
    2,6,10,14,31,27,23,19,3,7,11,15,30,26,22,18};

__device__ __forceinline__ u64 pack2(float x, float y) {
    u64 r; asm("mov.b64 %0, {%1, %2};" : "=l"(r) : "f"(x), "f"(y)); return r;
}
__device__ __forceinline__ u64 pack2u(u32 lo, u32 hi) {
    u64 r; asm("mov.b64 %0, {%1, %2};" : "=l"(r) : "r"(lo), "r"(hi)); return r;
}
__device__ __forceinline__ u32 tf32r(float x) {
    u32 r; asm("cvt.rna.tf32.f32 %0, %1;" : "=r"(r) : "f"(x)); return r;
}
__device__ __forceinline__ u32 f2u(float x) { return __float_as_uint(x); }
__device__ __forceinline__ float u2f(u32 x) { return __uint_as_float(x); }
__device__ __forceinline__ void mma8(float* c, u32 a0, u32 a1, u32 a2, u32 a3,
                                     u32 b0, u32 b1) {
    asm volatile(
        "mma.sync.aligned.m16n8k8.row.col.f32.tf32.tf32.f32 "
        "{%0,%1,%2,%3}, {%4,%5,%6,%7}, {%8,%9}, {%0,%1,%2,%3};"
        : "+f"(c[0]), "+f"(c[1]), "+f"(c[2]), "+f"(c[3])
        : "r"(a0), "r"(a1), "r"(a2), "r"(a3), "r"(b0), "r"(b1));
}

// ============================================================================
// Projection via tf32 mma. Block = 128 rows x N cols, K=1024, BK=16.
// NB=8: Y = X@W0 -> T0 (Q).   NB=16: Y = X@[W0|W1] -> T0 (K), T1 (V).
// XS row-major [r][k] stride 20; WS k-major [k][n] stride NB*8+4.
// Epilogue: tf32-round, transpose through smem, store [b*64+h][t].
// ============================================================================
template<int NB>
__device__ __forceinline__ void proj_body(
    const float* __restrict__ X, const float* __restrict__ W0,
    const float* __restrict__ W1, float* T0, float* T1,
    int row0, float* SM)
{
    const int WSS = NB * 8 + 4;           // 68 or 132
    float* XS = SM;                        // 128*20 = 2560
    float* WS = SM + 2560;                 // 16*WSS <= 2112
    float* ES = SM;                        // epilogue 64*132 = 8448

    const int tid  = threadIdx.x;
    const int wid  = tid >> 5;
    const int lane = tid & 31;
    const int grp  = lane >> 2;
    const int t4   = lane & 3;
    const int rb   = wid << 4;            // warp row stripe base

    // fill-index precompute
    const int xr_r  = tid >> 2;           // X row (two loads: f, f+256 -> r, r+64)
    const int xr_k  = (tid & 3) << 2;
    const int wk8   = tid >> 4;           // NB==8 W fill
    const int wc8   = (tid & 15) << 2;
    const int wk16  = tid >> 5;           // NB==16 W fill (i: +8 rows)
    const int wn16  = (tid & 31) << 2;

    float acc[NB][4];
    #pragma unroll
    for (int nb = 0; nb < NB; nb++)
        #pragma unroll
        for (int j = 0; j < 4; j++) acc[nb][j] = 0.f;

    float4 xr[2], wr[2];

    // preload tile 0
    #pragma unroll
    for (int i = 0; i < 2; i++)
        xr[i] = *(const float4*)(X + (size_t)(row0 + xr_r + i * 64) * EMB + xr_k);
    if (NB == 8) {
        wr[0] = *(const float4*)(W0 + (size_t)wk8 * HS + wc8);
    } else {
        #pragma unroll
        for (int i = 0; i < 2; i++) {
            int kk = wk16 + i * 8;
            wr[i] = (wn16 < 64)
                ? *(const float4*)(W0 + (size_t)kk * HS + wn16)
                : *(const float4*)(W1 + (size_t)kk * HS + wn16 - 64);
        }
    }
    #pragma unroll
    for (int i = 0; i < 2; i++)
        *(float4*)&XS[(xr_r + i * 64) * 20 + xr_k] = xr[i];
    if (NB == 8) {
        *(float4*)&WS[wk8 * WSS + wc8] = wr[0];
    } else {
        #pragma unroll
        for (int i = 0; i < 2; i++)
            *(float4*)&WS[(wk16 + i * 8) * WSS + wn16] = wr[i];
    }
    __syncthreads();

    for (int t = 0; t < 64; t++) {
        if (t < 63) {
            const int k0 = (t + 1) * 16;
            #pragma unroll
            for (int i = 0; i < 2; i++)
                xr[i] = *(const float4*)(X + (size_t)(row0 + xr_r + i * 64) * EMB + k0 + xr_k);
            if (NB == 8) {
                wr[0] = *(const float4*)(W0 + (size_t)(k0 + wk8) * HS + wc8);
            } else {
                #pragma unroll
                for (int i = 0; i < 2; i++) {
                    int kk = k0 + wk16 + i * 8;
                    wr[i] = (wn16 < 64)
                        ? *(const float4*)(W0 + (size_t)kk * HS + wn16)
                        : *(const float4*)(W1 + (size_t)kk * HS + wn16 - 64);
                }
            }
        }

        #pragma unroll
        for (int ks = 0; ks < 2; ks++) {
            const int k0 = ks * 8;
            const int ax = (rb + grp) * 20 + k0 + t4;
            u32 a0 = f2u(XS[ax]);
            u32 a1 = f2u(XS[ax + 160]);     // +8 rows
            u32 a2 = f2u(XS[ax + 4]);
            u32 a3 = f2u(XS[ax + 164]);
            #pragma unroll
            for (int nb = 0; nb < NB; nb++) {
                u32 b0 = f2u(WS[(k0 + t4) * WSS + nb * 8 + grp]);
                u32 b1 = f2u(WS[(k0 + t4 + 4) * WSS + nb * 8 + grp]);
                mma8(acc[nb], a0, a1, a2, a3, b0, b1);
            }
        }
        __syncthreads();
        if (t < 63) {
            #pragma unroll
            for (int i = 0; i < 2; i++)
                *(float4*)&XS[(xr_r + i * 64) * 20 + xr_k] = xr[i];
            if (NB == 8) {
                *(float4*)&WS[wk8 * WSS + wc8] = wr[0];
            } else {
                #pragma unroll
                for (int i = 0; i < 2; i++)
                    *(float4*)&WS[(wk16 + i * 8) * WSS + wn16] = wr[i];
            }
            __syncthreads();
        }
    }

    // epilogue: one or two 64-col transpose rounds
    const int bglob = row0 >> 11;
    const int trow  = row0 & 2047;
    #pragma unroll
    for (int rd = 0; rd < NB / 8; rd++) {
        float* T = (rd == 0) ? T0 : T1;
        __syncthreads();
        #pragma unroll
        for (int nb = 0; nb < 8; nb++) {
            const int nn = rd * 8 + nb;
            const int h2 = nb * 8 + 2 * t4;
            ES[h2 * 132 + rb + grp]           = u2f(tf32r(acc[nn][0]));
            ES[(h2 + 1) * 132 + rb + grp]     = u2f(tf32r(acc[nn][1]));
            ES[h2 * 132 + rb + grp + 8]       = u2f(tf32r(acc[nn][2]));
            ES[(h2 + 1) * 132 + rb + grp + 8] = u2f(tf32r(acc[nn][3]));
        }
        __syncthreads();
        #pragma unroll
        for (int i = 0; i < 8; i++) {
            int f  = tid + i * 256;
            int h  = f >> 5;
            int r4 = (f & 31) << 2;
            *(float4*)(T + (size_t)(bglob * 64 + h) * SEQ + trow + r4) =
                *(const float4*)&ES[h * 132 + r4];
        }
    }
}

__global__ __launch_bounds__(256, 2) void proj_kernel(
    const float* __restrict__ Xq, const float* __restrict__ Xkv,
    const float* __restrict__ Wq, const float* __restrict__ Wk,
    const float* __restrict__ Wv)
{
    __shared__ float SM[8448];
    const int row0 = blockIdx.x * 128;
    if (blockIdx.y == 0)
        proj_body<8>(Xq, Wq, (const float*)0, g_Qt, (float*)0, row0, SM);
    else
        proj_body<16>(Xkv, Wk, Wv, g_Kt, g_Vt, row0, SM);
}

// ============================================================================
// Flash attention, warp-specialized: warps 0-3 QK(kt)+softmax, warps 4-7
// PV(kt-1), overlapped via double-buffered P/V/rowstats. All mma tf32.
// ============================================================================
#define AQS  0
#define AKS  4608
#define AVS0 9216
#define AVS1 13568
#define APS0 17920
#define APS1 22272
#define ANM0 26624
#define ANM1 26688
#define ANS0 26752
#define ANS1 26816
#define ASM_F 26880   // floats (107520 bytes)

__global__ __launch_bounds__(256, 2) void attn_kernel(float* __restrict__ out)
{
    extern __shared__ float sm[];
    const int tid  = threadIdx.x;
    const int wid  = tid >> 5;
    const int lane = tid & 31;
    const int grp  = lane >> 2;
    const int t4   = lane & 3;
    const int rb   = (wid & 3) << 4;     // 16-row stripe base (both roles)
    const int r0   = rb + grp;
    const int dd   = tid >> 4;
    const int c4   = (tid & 15) << 2;

    const int b = blockIdx.y;
    const int qt = qt_map[blockIdx.x];
    const int qrow0 = qt * 64;
    const float scale = 0.03125f;        // 1/sqrt(1024)

    const float* Qg = g_Qt + (size_t)(b * 64) * SEQ + qrow0;
    const float* Kg = g_Kt + (size_t)(b * 64) * SEQ;
    const float* Vg = g_Vt + (size_t)(b * 64) * SEQ;

    // stage Q: [d][r] stride 72, straight copy
    #pragma unroll
    for (int i = 0; i < 4; i++) {
        int d = dd + i * 16;
        *(float4*)&sm[AQS + d * 72 + c4] = *(const float4*)(Qg + (size_t)d * SEQ + c4);
    }

    float acc[8][4];                     // PV warps: O stripe (16 rows x 64 h)
    #pragma unroll
    for (int nb = 0; nb < 8; nb++)
        #pragma unroll
        for (int j = 0; j < 4; j++) acc[nb][j] = 0.f;
    float mq0 = -1e30f, mq1 = -1e30f;    // QK running max
    float mpv0 = -1e30f, mpv1 = -1e30f;  // PV applied max
    float l0 = 0.f, l1 = 0.f;

    for (int kt = 0; kt <= qt; kt++) {
        __syncthreads();
        const int bf = kt & 1;
        float* VSb = sm + (bf ? AVS1 : AVS0);
        #pragma unroll
        for (int i = 0; i < 4; i++) {
            int d = dd + i * 16;
            *(float4*)&sm[AKS + d * 72 + c4] =
                *(const float4*)(Kg + (size_t)d * SEQ + kt * 64 + c4);
            *(float4*)&VSb[d * 68 + c4] =
                *(const float4*)(Vg + (size_t)d * SEQ + kt * 64 + c4);
        }
        __syncthreads();

        if (wid < 4) {
            // ---- QK + softmax ----
            float S[8][4];
            #pragma unroll
            for (int nb = 0; nb < 8; nb++)
                #pragma unroll
                for (int j = 0; j < 4; j++) S[nb][j] = 0.f;

            #pragma unroll
            for (int kk = 0; kk < 8; kk++) {
                const int d0 = kk * 8;
                u32 a0 = f2u(sm[AQS + (d0 + t4) * 72 + r0]);
                u32 a1 = f2u(sm[AQS + (d0 + t4) * 72 + r0 + 8]);
                u32 a2 = f2u(sm[AQS + (d0 + t4 + 4) * 72 + r0]);
                u32 a3 = f2u(sm[AQS + (d0 + t4 + 4) * 72 + r0 + 8]);
                #pragma unroll
                for (int nb = 0; nb < 8; nb++) {
                    u32 b0 = f2u(sm[AKS + (d0 + t4) * 72 + nb * 8 + grp]);
                    u32 b1 = f2u(sm[AKS + (d0 + t4 + 4) * 72 + nb * 8 + grp]);
                    mma8(S[nb], a0, a1, a2, a3, b0, b1);
                }
            }
            #pragma unroll
            for (int nb = 0; nb < 8; nb++)
                #pragma unroll
                for (int j = 0; j < 4; j++) S[nb][j] *= scale;

            if (kt == qt) {
                #pragma unroll
                for (int nb = 0; nb < 8; nb++) {
                    int c0 = nb * 8 + 2 * t4;
                    if (c0     > r0)     S[nb][0] = -1e30f;
                    if (c0 + 1 > r0)     S[nb][1] = -1e30f;
                    if (c0     > r0 + 8) S[nb][2] = -1e30f;
                    if (c0 + 1 > r0 + 8) S[nb][3] = -1e30f;
                }
            }

            float mx0 = -1e30f, mx1 = -1e30f;
            #pragma unroll
            for (int nb = 0; nb < 8; nb++) {
                mx0 = fmaxf(mx0, fmaxf(S[nb][0], S[nb][1]));
                mx1 = fmaxf(mx1, fmaxf(S[nb][2], S[nb][3]));
            }
            mx0 = fmaxf(mx0, __shfl_xor_sync(0xffffffffu, mx0, 1));
            mx0 = fmaxf(mx0, __shfl_xor_sync(0xffffffffu, mx0, 2));
            mx1 = fmaxf(mx1, __shfl_xor_sync(0xffffffffu, mx1, 1));
            mx1 = fmaxf(mx1, __shfl_xor_sync(0xffffffffu, mx1, 2));
            const float gm0 = fmaxf(mq0, mx0);
            const float gm1 = fmaxf(mq1, mx1);
            mq0 = gm0; mq1 = gm1;

            float* PSb = sm + (bf ? APS1 : APS0);
            float s0 = 0.f, s1 = 0.f;
            #pragma unroll
            for (int nb = 0; nb < 8; nb++) {
                u32 p0 = tf32r(__expf(S[nb][0] - gm0));
                u32 p1 = tf32r(__expf(S[nb][1] - gm0));
                u32 p2 = tf32r(__expf(S[nb][2] - gm1));
                u32 p3 = tf32r(__expf(S[nb][3] - gm1));
                s0 += u2f(p0) + u2f(p1);
                s1 += u2f(p2) + u2f(p3);
                *(u64*)&PSb[r0 * 68 + nb * 8 + 2 * t4]       = pack2u(p0, p1);
                *(u64*)&PSb[(r0 + 8) * 68 + nb * 8 + 2 * t4] = pack2u(p2, p3);
            }
            s0 += __shfl_xor_sync(0xffffffffu, s0, 1);
            s0 += __shfl_xor_sync(0xffffffffu, s0, 2);
            s1 += __shfl_xor_sync(0xffffffffu, s1, 1);
            s1 += __shfl_xor_sync(0xffffffffu, s1, 2);
            if (t4 == 0) {
                sm[(bf ? ANM1 : ANM0) + r0]     = gm0;
                sm[(bf ? ANM1 : ANM0) + r0 + 8] = gm1;
                sm[(bf ? ANS1 : ANS0) + r0]     = s0;
                sm[(bf ? ANS1 : ANS0) + r0 + 8] = s1;
            }
        } else if (kt > 0) {
            // ---- PV of tile kt-1 ----
            const int pb = (kt - 1) & 1;
            float* PSb = sm + (pb ? APS1 : APS0);
            float* VSp = sm + (pb ? AVS1 : AVS0);
            float nm0 = sm[(pb ? ANM1 : ANM0) + r0];
            float nm1 = sm[(pb ? ANM1 : ANM0) + r0 + 8];
            float ns0 = sm[(pb ? ANS1 : ANS0) + r0];
            float ns1 = sm[(pb ? ANS1 : ANS0) + r0 + 8];
            float c0 = __expf(mpv0 - nm0), c1 = __expf(mpv1 - nm1);
            mpv0 = nm0; mpv1 = nm1;
            l0 = l0 * c0 + ns0;
            l1 = l1 * c1 + ns1;
            #pragma unroll
            for (int nb = 0; nb < 8; nb++) {
                acc[nb][0] *= c0; acc[nb][1] *= c0;
                acc[nb][2] *= c1; acc[nb][3] *= c1;
            }
            #pragma unroll
            for (int ks = 0; ks < 8; ks++) {
                const int k0 = ks * 8;
                const int ax = r0 * 68 + k0 + t4;
                u32 a0 = f2u(PSb[ax]);
                u32 a1 = f2u(PSb[ax + 8 * 68]);
                u32 a2 = f2u(PSb[ax + 4]);
                u32 a3 = f2u(PSb[ax + 8 * 68 + 4]);
                #pragma unroll
                for (int nb = 0; nb < 8; nb++) {
                    u32 b0 = f2u(VSp[(nb * 8 + grp) * 68 + k0 + t4]);
                    u32 b1 = f2u(VSp[(nb * 8 + grp) * 68 + k0 + t4 + 4]);
                    mma8(acc[nb], a0, a1, a2, a3, b0, b1);
                }
            }
        }
    }

    // ---- drain PV(qt) + epilogue ----
    __syncthreads();
    if (wid >= 4) {
        const int pb = qt & 1;
        float* PSb = sm + (pb ? APS1 : APS0);
        float* VSp = sm + (pb ? AVS1 : AVS0);
        float nm0 = sm[(pb ? ANM1 : ANM0) + r0];
        float nm1 = sm[(pb ? ANM1 : ANM0) + r0 + 8];
        float ns0 = sm[(pb ? ANS1 : ANS0) + r0];
        float ns1 = sm[(pb ? ANS1 : ANS0) + r0 + 8];
        float c0 = __expf(mpv0 - nm0), c1 = __expf(mpv1 - nm1);
        l0 = l0 * c0 + ns0;
        l1 = l1 * c1 + ns1;
        #pragma unroll
        for (int nb = 0; nb < 8; nb++) {
            acc[nb][0] *= c0; acc[nb][1] *= c0;
            acc[nb][2] *= c1; acc[nb][3] *= c1;
        }
        #pragma unroll
        for (int ks = 0; ks < 8; ks++) {
            const int k0 = ks * 8;
            const int ax = r0 * 68 + k0 + t4;
            u32 a0 = f2u(PSb[ax]);
            u32 a1 = f2u(PSb[ax + 8 * 68]);
            u32 a2 = f2u(PSb[ax + 4]);
            u32 a3 = f2u(PSb[ax + 8 * 68 + 4]);
            #pragma unroll
            for (int nb = 0; nb < 8; nb++) {
                u32 b0 = f2u(VSp[(nb * 8 + grp) * 68 + k0 + t4]);
                u32 b1 = f2u(VSp[(nb * 8 + grp) * 68 + k0 + t4 + 4]);
                mma8(acc[nb], a0, a1, a2, a3, b0, b1);
            }
        }
        const float inv0 = 1.0f / l0, inv1 = 1.0f / l1;
        float* o0 = out + ((size_t)b * SEQ + qrow0 + r0) * HS;
        float* o8 = o0 + 8 * HS;
        #pragma unroll
        for (int nb = 0; nb < 8; nb++) {
            *(u64*)(o0 + nb * 8 + 2 * t4) = pack2(acc[nb][0] * inv0, acc[nb][1] * inv0);
            *(u64*)(o8 + nb * 8 + 2 * t4) = pack2(acc[nb][2] * inv1, acc[nb][3] * inv1);
        }
    }
}

extern "C" void kernel_launch(void* const* d_in, const int* in_sizes, int n_in,
                              void* d_out, int out_size)
{
    (void)in_sizes; (void)n_in; (void)out_size;
    const float* index  = (const float*)d_in[0];
    const float* memory = (const float*)d_in[1];
    const float* Wq     = (const float*)d_in[2];
    const float* Wk     = (const float*)d_in[3];
    const float* Wv     = (const float*)d_in[4];
    float* out = (float*)d_out;

    cudaFuncSetAttribute(attn_kernel,
                         cudaFuncAttributeMaxDynamicSharedMemorySize,
                         ASM_F * 4);

    proj_kernel<<<dim3(128, 2), 256>>>(index, memory, Wq, Wk, Wv);
    attn_kernel<<<dim3(32, 8), 256, ASM_F * 4>>>(out);
}